// round 4
// baseline (speedup 1.0000x reference)
#include <cuda_runtime.h>

#define N_USERS  100000
#define N_ITEMS  50000
#define N_TOTAL  150000
#define DIM      64
#define NNZ      1200000
#define BATCH    4096
#define TILE     1024
#define NTILES   ((N_TOTAL + TILE - 1) / TILE)   // 147

// ---- scratch (device globals; no allocation allowed) ----
__device__ int   g_count[N_TOTAL];
__device__ int   g_rowptr[N_TOTAL + 1];
__device__ int   g_cursor[N_TOTAL];
__device__ unsigned long long g_tstate[NTILES];  // lookback state: flag<<32 | value
__device__ int2  g_csr[NNZ];                     // {col, val bits} interleaved
__device__ float g_E1[N_TOTAL * DIM];
__device__ float g_E2[N_TOTAL * DIM];

// ---------------- CSR build ----------------

__global__ void k_zero() {
    int i = blockIdx.x * blockDim.x + threadIdx.x;
    if (i < N_TOTAL) g_count[i] = 0;
    if (i < NTILES)  g_tstate[i] = 0ull;
}

__global__ void k_hist(const int* __restrict__ row) {
    int e = blockIdx.x * blockDim.x + threadIdx.x;
    if (e < NNZ) atomicAdd(&g_count[row[e]], 1);
}

// single-pass exclusive scan with decoupled lookback (fuses old scan1/2/3)
__global__ void __launch_bounds__(TILE) k_scan() {
    __shared__ int wsum[32];
    __shared__ int s_running;
    int b    = blockIdx.x;
    int tid  = threadIdx.x;
    int lane = tid & 31, wid = tid >> 5;
    int gi   = b * TILE + tid;
    int v    = (gi < N_TOTAL) ? g_count[gi] : 0;

    // warp inclusive scan
    int x = v;
    #pragma unroll
    for (int off = 1; off < 32; off <<= 1) {
        int t = __shfl_up_sync(0xffffffffu, x, off);
        if (lane >= off) x += t;
    }
    if (lane == 31) wsum[wid] = x;
    __syncthreads();
    if (wid == 0) {
        int s = wsum[lane];
        #pragma unroll
        for (int off = 1; off < 32; off <<= 1) {
            int t = __shfl_up_sync(0xffffffffu, s, off);
            if (lane >= off) s += t;
        }
        wsum[lane] = s;   // inclusive warp totals
    }
    __syncthreads();
    int incl  = x + (wid ? wsum[wid - 1] : 0);   // inclusive scan within tile
    int total = wsum[31];

    if (tid == 0) {
        volatile unsigned long long* st = (volatile unsigned long long*)g_tstate;
        if (b == 0) {
            __threadfence();
            st[0] = (2ull << 32) | (unsigned)total;
            s_running = 0;
        } else {
            __threadfence();
            st[b] = (1ull << 32) | (unsigned)total;
            int running = 0;
            int p = b - 1;
            while (true) {
                unsigned long long s = st[p];
                unsigned flag = (unsigned)(s >> 32);
                if (flag == 0u) continue;          // predecessor not published yet
                running += (int)(unsigned)s;
                if (flag == 2u) break;             // inclusive prefix — done
                --p;                               // aggregate — keep looking back
            }
            __threadfence();
            st[b] = (2ull << 32) | (unsigned)(running + total);
            s_running = running;
        }
    }
    __syncthreads();
    int run = s_running;
    if (gi < N_TOTAL) {
        int excl = incl - v + run;
        g_rowptr[gi] = excl;
        g_cursor[gi] = excl;
        if (gi == N_TOTAL - 1) g_rowptr[N_TOTAL] = incl + run;   // == NNZ
    }
}

__global__ void k_scatter(const int* __restrict__ row,
                          const int* __restrict__ col,
                          const float* __restrict__ val) {
    int e = blockIdx.x * blockDim.x + threadIdx.x;
    if (e < NNZ) {
        int r = row[e];
        int p = atomicAdd(&g_cursor[r], 1);
        g_csr[p] = make_int2(col[e], __float_as_int(val[e]));
    }
}

// ---------------- SpMM: one warp per row, lane handles float2 {2*lane, 2*lane+1} ----------------

__device__ __forceinline__ float2 row_gemv(const float* __restrict__ E, int r, int lane) {
    int s = g_rowptr[r];
    int e = g_rowptr[r + 1];
    float2 acc = make_float2(0.f, 0.f);
    int j = s;
    for (; j + 2 <= e; j += 2) {
        int2 cv0 = g_csr[j];
        int2 cv1 = g_csr[j + 1];
        const float2* __restrict__ e0 = (const float2*)(E + (size_t)cv0.x * DIM);
        const float2* __restrict__ e1 = (const float2*)(E + (size_t)cv1.x * DIM);
        float2 x0 = e0[lane];
        float2 x1 = e1[lane];
        float v0 = __int_as_float(cv0.y), v1 = __int_as_float(cv1.y);
        acc.x = fmaf(v0, x0.x, acc.x); acc.y = fmaf(v0, x0.y, acc.y);
        acc.x = fmaf(v1, x1.x, acc.x); acc.y = fmaf(v1, x1.y, acc.y);
    }
    if (j < e) {
        int2 cv = g_csr[j];
        const float2* __restrict__ e0 = (const float2*)(E + (size_t)cv.x * DIM);
        float2 x0 = e0[lane];
        float v0 = __int_as_float(cv.y);
        acc.x = fmaf(v0, x0.x, acc.x); acc.y = fmaf(v0, x0.y, acc.y);
    }
    return acc;
}

__global__ void __launch_bounds__(256) k_spmm1(const float* __restrict__ E0) {
    int w    = (blockIdx.x * blockDim.x + threadIdx.x) >> 5;
    int lane = threadIdx.x & 31;
    if (w >= N_TOTAL) return;
    float2 a = row_gemv(E0, w, lane);
    ((float2*)(g_E1 + (size_t)w * DIM))[lane] = a;
}

__global__ void __launch_bounds__(256) k_spmm2() {
    int w    = (blockIdx.x * blockDim.x + threadIdx.x) >> 5;
    int lane = threadIdx.x & 31;
    if (w >= N_TOTAL) return;
    float2 a = row_gemv(g_E1, w, lane);
    ((float2*)(g_E2 + (size_t)w * DIM))[lane] = a;
}

// ---------------- fused layer-3 + average + gather ----------------
// out slots: 0 u_emb, 1 pos_emb, 2 neg_emb, 3 u_emb0, 4 pos_emb0, 5 neg_emb0
__global__ void __launch_bounds__(256) k_gather(const int* __restrict__ users,
                                                const int* __restrict__ pos,
                                                const int* __restrict__ neg,
                                                const float* __restrict__ E0,
                                                float* __restrict__ out) {
    int w    = (blockIdx.x * blockDim.x + threadIdx.x) >> 5;
    int lane = threadIdx.x & 31;
    if (w >= 3 * BATCH) return;
    int slot = w / BATCH;
    int b    = w - slot * BATCH;
    int r;
    if (slot == 0)      r = users[b];
    else if (slot == 1) r = N_USERS + pos[b];
    else                r = N_USERS + neg[b];

    // E3 row = (A @ E2)[r] — only needed at gathered rows
    float2 a = row_gemv(g_E2, r, lane);

    const float2* __restrict__ pe0 = (const float2*)(E0  + (size_t)r * DIM);
    const float2* __restrict__ pe1 = (const float2*)(g_E1 + (size_t)r * DIM);
    const float2* __restrict__ pe2 = (const float2*)(g_E2 + (size_t)r * DIM);
    float2 e0 = pe0[lane], e1 = pe1[lane], e2 = pe2[lane];
    float2 f;
    f.x = (e0.x + e1.x + e2.x + a.x) * 0.25f;
    f.y = (e0.y + e1.y + e2.y + a.y) * 0.25f;

    float2* o  = (float2*)(out + (size_t)slot * BATCH * DIM + (size_t)b * DIM);
    float2* o0 = (float2*)(out + (size_t)(slot + 3) * BATCH * DIM + (size_t)b * DIM);
    o[lane]  = f;
    o0[lane] = e0;
}

// ---------------- launch ----------------

extern "C" void kernel_launch(void* const* d_in, const int* in_sizes, int n_in,
                              void* d_out, int out_size) {
    const int*   users = (const int*)  d_in[0];
    const int*   pos   = (const int*)  d_in[1];
    const int*   neg   = (const int*)  d_in[2];
    const float* E0    = (const float*)d_in[3];
    const int*   arow  = (const int*)  d_in[4];
    const int*   acol  = (const int*)  d_in[5];
    const float* avals = (const float*)d_in[6];
    float* out = (float*)d_out;

    k_zero<<<(N_TOTAL + 255) / 256, 256>>>();
    k_hist<<<(NNZ + 255) / 256, 256>>>(arow);
    k_scan<<<NTILES, TILE>>>();
    k_scatter<<<(NNZ + 255) / 256, 256>>>(arow, acol, avals);

    const int spmm_blocks = (N_TOTAL * 32 + 255) / 256;   // 1 warp per row
    k_spmm1<<<spmm_blocks, 256>>>(E0);
    k_spmm2<<<spmm_blocks, 256>>>();

    const int gat_blocks = (3 * BATCH * 32 + 255) / 256;
    k_gather<<<gat_blocks, 256>>>(users, pos, neg, E0, out);
}

// round 5
// speedup vs baseline: 1.3005x; 1.3005x over previous
#include <cuda_runtime.h>

#define N_USERS  100000
#define N_ITEMS  50000
#define N_TOTAL  150000
#define DIM      64
#define NNZ      1200000
#define BATCH    4096
#define SCAN_B   1024
#define NBLK_SCAN ((N_TOTAL + SCAN_B - 1) / SCAN_B)   // 147

// ---- scratch (device globals; no allocation allowed) ----
__device__ int   g_count[N_TOTAL];
__device__ int   g_rowptr[N_TOTAL + 1];
__device__ int   g_cursor[N_TOTAL];
__device__ int   g_bsum[NBLK_SCAN];
__device__ int2  g_csr[NNZ];                     // {col, val bits} interleaved
__device__ float g_E1[N_TOTAL * DIM];
__device__ float g_E2[N_TOTAL * DIM];

// ---------------- CSR build ----------------

__global__ void k_zero() {
    int i = blockIdx.x * blockDim.x + threadIdx.x;
    if (i < N_TOTAL) g_count[i] = 0;
}

// 4 edges per thread — 4 independent atomics in flight (latency-bound fix)
__global__ void k_hist(const int4* __restrict__ row4) {
    int t = blockIdx.x * blockDim.x + threadIdx.x;
    if (t < NNZ / 4) {
        int4 r = row4[t];
        atomicAdd(&g_count[r.x], 1);
        atomicAdd(&g_count[r.y], 1);
        atomicAdd(&g_count[r.z], 1);
        atomicAdd(&g_count[r.w], 1);
    }
}

// per-block exclusive scan; block totals to g_bsum
__global__ void __launch_bounds__(SCAN_B) k_scan1() {
    __shared__ int sh[SCAN_B];
    int i = blockIdx.x * SCAN_B + threadIdx.x;
    int v = (i < N_TOTAL) ? g_count[i] : 0;
    sh[threadIdx.x] = v;
    __syncthreads();
    #pragma unroll
    for (int off = 1; off < SCAN_B; off <<= 1) {
        int t = (threadIdx.x >= off) ? sh[threadIdx.x - off] : 0;
        __syncthreads();
        sh[threadIdx.x] += t;
        __syncthreads();
    }
    if (i < N_TOTAL) g_rowptr[i] = sh[threadIdx.x] - v;     // exclusive within block
    if (threadIdx.x == SCAN_B - 1) g_bsum[blockIdx.x] = sh[SCAN_B - 1];
}

// warp-parallel scan of the 147 block sums (was 1 thread @ 7.4us)
__global__ void k_scan2() {
    int lane = threadIdx.x;   // 32 threads
    int carry = 0;
    for (int base = 0; base < NBLK_SCAN; base += 32) {
        int i = base + lane;
        int v = (i < NBLK_SCAN) ? g_bsum[i] : 0;
        int x = v;
        #pragma unroll
        for (int off = 1; off < 32; off <<= 1) {
            int t = __shfl_up_sync(0xffffffffu, x, off);
            if (lane >= off) x += t;
        }
        if (i < NBLK_SCAN) g_bsum[i] = x - v + carry;       // exclusive + carry
        carry += __shfl_sync(0xffffffffu, x, 31);
    }
}

__global__ void k_scan3() {
    int i = blockIdx.x * blockDim.x + threadIdx.x;
    if (i < N_TOTAL) {
        int p = g_rowptr[i] + g_bsum[i / SCAN_B];
        g_rowptr[i] = p;
        g_cursor[i] = p;
    }
    if (i == 0) g_rowptr[N_TOTAL] = NNZ;
}

// 4 edges per thread — vectorized loads, 4 independent atomic+store chains
__global__ void k_scatter(const int4* __restrict__ row4,
                          const int4* __restrict__ col4,
                          const float4* __restrict__ val4) {
    int t = blockIdx.x * blockDim.x + threadIdx.x;
    if (t < NNZ / 4) {
        int4   r = row4[t];
        int4   c = col4[t];
        float4 v = val4[t];
        int p0 = atomicAdd(&g_cursor[r.x], 1);
        int p1 = atomicAdd(&g_cursor[r.y], 1);
        int p2 = atomicAdd(&g_cursor[r.z], 1);
        int p3 = atomicAdd(&g_cursor[r.w], 1);
        g_csr[p0] = make_int2(c.x, __float_as_int(v.x));
        g_csr[p1] = make_int2(c.y, __float_as_int(v.y));
        g_csr[p2] = make_int2(c.z, __float_as_int(v.z));
        g_csr[p3] = make_int2(c.w, __float_as_int(v.w));
    }
}

// ---------------- SpMM: one warp per row, lane handles float2 {2*lane, 2*lane+1} ----------------

__device__ __forceinline__ float2 row_gemv(const float* __restrict__ E, int r, int lane) {
    int s = g_rowptr[r];
    int e = g_rowptr[r + 1];
    float2 acc = make_float2(0.f, 0.f);
    int j = s;
    for (; j + 2 <= e; j += 2) {
        int2 cv0 = g_csr[j];
        int2 cv1 = g_csr[j + 1];
        const float2* __restrict__ e0 = (const float2*)(E + (size_t)cv0.x * DIM);
        const float2* __restrict__ e1 = (const float2*)(E + (size_t)cv1.x * DIM);
        float2 x0 = e0[lane];
        float2 x1 = e1[lane];
        float v0 = __int_as_float(cv0.y), v1 = __int_as_float(cv1.y);
        acc.x = fmaf(v0, x0.x, acc.x); acc.y = fmaf(v0, x0.y, acc.y);
        acc.x = fmaf(v1, x1.x, acc.x); acc.y = fmaf(v1, x1.y, acc.y);
    }
    if (j < e) {
        int2 cv = g_csr[j];
        const float2* __restrict__ e0 = (const float2*)(E + (size_t)cv.x * DIM);
        float2 x0 = e0[lane];
        float v0 = __int_as_float(cv.y);
        acc.x = fmaf(v0, x0.x, acc.x); acc.y = fmaf(v0, x0.y, acc.y);
    }
    return acc;
}

__global__ void __launch_bounds__(256) k_spmm1(const float* __restrict__ E0) {
    int w    = (blockIdx.x * blockDim.x + threadIdx.x) >> 5;
    int lane = threadIdx.x & 31;
    if (w >= N_TOTAL) return;
    float2 a = row_gemv(E0, w, lane);
    ((float2*)(g_E1 + (size_t)w * DIM))[lane] = a;
}

__global__ void __launch_bounds__(256) k_spmm2() {
    int w    = (blockIdx.x * blockDim.x + threadIdx.x) >> 5;
    int lane = threadIdx.x & 31;
    if (w >= N_TOTAL) return;
    float2 a = row_gemv(g_E1, w, lane);
    ((float2*)(g_E2 + (size_t)w * DIM))[lane] = a;
}

// ---------------- fused layer-3 + average + gather ----------------
// out slots: 0 u_emb, 1 pos_emb, 2 neg_emb, 3 u_emb0, 4 pos_emb0, 5 neg_emb0
__global__ void __launch_bounds__(256) k_gather(const int* __restrict__ users,
                                                const int* __restrict__ pos,
                                                const int* __restrict__ neg,
                                                const float* __restrict__ E0,
                                                float* __restrict__ out) {
    int w    = (blockIdx.x * blockDim.x + threadIdx.x) >> 5;
    int lane = threadIdx.x & 31;
    if (w >= 3 * BATCH) return;
    int slot = w / BATCH;
    int b    = w - slot * BATCH;
    int r;
    if (slot == 0)      r = users[b];
    else if (slot == 1) r = N_USERS + pos[b];
    else                r = N_USERS + neg[b];

    // E3 row = (A @ E2)[r] — only needed at gathered rows
    float2 a = row_gemv(g_E2, r, lane);

    const float2* __restrict__ pe0 = (const float2*)(E0   + (size_t)r * DIM);
    const float2* __restrict__ pe1 = (const float2*)(g_E1 + (size_t)r * DIM);
    const float2* __restrict__ pe2 = (const float2*)(g_E2 + (size_t)r * DIM);
    float2 e0 = pe0[lane], e1 = pe1[lane], e2 = pe2[lane];
    float2 f;
    f.x = (e0.x + e1.x + e2.x + a.x) * 0.25f;
    f.y = (e0.y + e1.y + e2.y + a.y) * 0.25f;

    float2* o  = (float2*)(out + (size_t)slot * BATCH * DIM + (size_t)b * DIM);
    float2* o0 = (float2*)(out + (size_t)(slot + 3) * BATCH * DIM + (size_t)b * DIM);
    o[lane]  = f;
    o0[lane] = e0;
}

// ---------------- launch ----------------

extern "C" void kernel_launch(void* const* d_in, const int* in_sizes, int n_in,
                              void* d_out, int out_size) {
    const int*   users = (const int*)  d_in[0];
    const int*   pos   = (const int*)  d_in[1];
    const int*   neg   = (const int*)  d_in[2];
    const float* E0    = (const float*)d_in[3];
    const int*   arow  = (const int*)  d_in[4];
    const int*   acol  = (const int*)  d_in[5];
    const float* avals = (const float*)d_in[6];
    float* out = (float*)d_out;

    const int e4_blocks = (NNZ / 4 + 255) / 256;   // 1172

    k_zero<<<(N_TOTAL + 255) / 256, 256>>>();
    k_hist<<<e4_blocks, 256>>>((const int4*)arow);
    k_scan1<<<NBLK_SCAN, SCAN_B>>>();
    k_scan2<<<1, 32>>>();
    k_scan3<<<(N_TOTAL + 255) / 256, 256>>>();
    k_scatter<<<e4_blocks, 256>>>((const int4*)arow, (const int4*)acol, (const float4*)avals);

    const int spmm_blocks = (N_TOTAL * 32 + 255) / 256;   // 1 warp per row
    k_spmm1<<<spmm_blocks, 256>>>(E0);
    k_spmm2<<<spmm_blocks, 256>>>();

    const int gat_blocks = (3 * BATCH * 32 + 255) / 256;
    k_gather<<<gat_blocks, 256>>>(users, pos, neg, E0, out);
}

// round 6
// speedup vs baseline: 1.5732x; 1.2097x over previous
#include <cuda_runtime.h>

#define N_USERS  100000
#define N_ITEMS  50000
#define N_TOTAL  150000
#define DIM      64
#define NNZ      1200000
#define BATCH    4096
#define SCAN_B   1024
#define NBLK_SCAN ((N_TOTAL + SCAN_B - 1) / SCAN_B)   // 147

// ---- scratch (device globals; no allocation allowed) ----
__device__ int      g_count[N_TOTAL];
__device__ int      g_rowptr[N_TOTAL + 1];
__device__ int      g_cursor[N_TOTAL];
__device__ int      g_bsum[NBLK_SCAN];
__device__ unsigned g_scan_done;                 // zero-init; reset by last block
__device__ int2     g_csr[NNZ];                  // {col, val bits} interleaved
__device__ float    g_E1[N_TOTAL * DIM];
__device__ float    g_E2[N_TOTAL * DIM];

// ---------------- CSR build ----------------

__global__ void k_zero() {
    int i = blockIdx.x * blockDim.x + threadIdx.x;
    if (i < N_TOTAL) g_count[i] = 0;
}

// 4 edges per thread — 4 independent atomics in flight
__global__ void k_hist(const int4* __restrict__ row4) {
    int t = blockIdx.x * blockDim.x + threadIdx.x;
    if (t < NNZ / 4) {
        int4 r = row4[t];
        atomicAdd(&g_count[r.x], 1);
        atomicAdd(&g_count[r.y], 1);
        atomicAdd(&g_count[r.z], 1);
        atomicAdd(&g_count[r.w], 1);
    }
}

// per-block exclusive scan; last block to finish also scans the block sums
__global__ void __launch_bounds__(SCAN_B) k_scan1() {
    __shared__ int  sh[SCAN_B];
    __shared__ bool is_last;
    int i = blockIdx.x * SCAN_B + threadIdx.x;
    int v = (i < N_TOTAL) ? g_count[i] : 0;
    sh[threadIdx.x] = v;
    __syncthreads();
    #pragma unroll
    for (int off = 1; off < SCAN_B; off <<= 1) {
        int t = (threadIdx.x >= off) ? sh[threadIdx.x - off] : 0;
        __syncthreads();
        sh[threadIdx.x] += t;
        __syncthreads();
    }
    if (i < N_TOTAL) g_rowptr[i] = sh[threadIdx.x] - v;     // exclusive within block
    if (threadIdx.x == SCAN_B - 1) g_bsum[blockIdx.x] = sh[SCAN_B - 1];

    // last-block-done: fold the old k_scan2 launch in here
    __threadfence();
    if (threadIdx.x == 0)
        is_last = (atomicAdd(&g_scan_done, 1u) == (unsigned)(gridDim.x - 1));
    __syncthreads();
    if (is_last && threadIdx.x < 32) {
        int lane = threadIdx.x;
        int carry = 0;
        for (int base = 0; base < NBLK_SCAN; base += 32) {
            int bi = base + lane;
            int bv = (bi < NBLK_SCAN) ? g_bsum[bi] : 0;
            int x = bv;
            #pragma unroll
            for (int off = 1; off < 32; off <<= 1) {
                int t = __shfl_up_sync(0xffffffffu, x, off);
                if (lane >= off) x += t;
            }
            if (bi < NBLK_SCAN) g_bsum[bi] = x - bv + carry;   // exclusive + carry
            carry += __shfl_sync(0xffffffffu, x, 31);
        }
        if (lane == 0) g_scan_done = 0u;                       // reset for next replay
    }
}

__global__ void k_scan3() {
    int i = blockIdx.x * blockDim.x + threadIdx.x;
    if (i < N_TOTAL) {
        int p = g_rowptr[i] + g_bsum[i / SCAN_B];
        g_rowptr[i] = p;
        g_cursor[i] = p;
    }
    if (i == 0) g_rowptr[N_TOTAL] = NNZ;
}

// 4 edges per thread — vectorized loads, 4 independent atomic+store chains
__global__ void k_scatter(const int4* __restrict__ row4,
                          const int4* __restrict__ col4,
                          const float4* __restrict__ val4) {
    int t = blockIdx.x * blockDim.x + threadIdx.x;
    if (t < NNZ / 4) {
        int4   r = row4[t];
        int4   c = col4[t];
        float4 v = val4[t];
        int p0 = atomicAdd(&g_cursor[r.x], 1);
        int p1 = atomicAdd(&g_cursor[r.y], 1);
        int p2 = atomicAdd(&g_cursor[r.z], 1);
        int p3 = atomicAdd(&g_cursor[r.w], 1);
        g_csr[p0] = make_int2(c.x, __float_as_int(v.x));
        g_csr[p1] = make_int2(c.y, __float_as_int(v.y));
        g_csr[p2] = make_int2(c.z, __float_as_int(v.z));
        g_csr[p3] = make_int2(c.w, __float_as_int(v.w));
    }
}

// ---------------- SpMM: one warp per row; lane covers dims {lane, lane+32} ----------------
// Scalar LDG.32 pairs on purpose: a 256B LDG.64 footprint pays the 2.07 cyc/wf
// within-LDG replay rate; two 128B LDG.32 issue at 1.0 cyc/wf (B300 L1tex model).

__device__ __forceinline__ void row_gemv(const float* __restrict__ E, int r, int lane,
                                         float& a0, float& a1) {
    int s = g_rowptr[r];
    int e = g_rowptr[r + 1];
    a0 = 0.f; a1 = 0.f;
    int j = s;
    for (; j + 2 <= e; j += 2) {
        int2 cv0 = g_csr[j];
        int2 cv1 = g_csr[j + 1];
        const float* __restrict__ e0 = E + (size_t)cv0.x * DIM;
        const float* __restrict__ e1 = E + (size_t)cv1.x * DIM;
        float x00 = e0[lane], x01 = e0[lane + 32];
        float x10 = e1[lane], x11 = e1[lane + 32];
        float v0 = __int_as_float(cv0.y), v1 = __int_as_float(cv1.y);
        a0 = fmaf(v0, x00, a0); a1 = fmaf(v0, x01, a1);
        a0 = fmaf(v1, x10, a0); a1 = fmaf(v1, x11, a1);
    }
    if (j < e) {
        int2 cv = g_csr[j];
        const float* __restrict__ e0 = E + (size_t)cv.x * DIM;
        float v0 = __int_as_float(cv.y);
        a0 = fmaf(v0, e0[lane],      a0);
        a1 = fmaf(v0, e0[lane + 32], a1);
    }
}

__global__ void __launch_bounds__(256) k_spmm1(const float* __restrict__ E0) {
    int w    = (blockIdx.x * blockDim.x + threadIdx.x) >> 5;
    int lane = threadIdx.x & 31;
    if (w >= N_TOTAL) return;
    float a0, a1;
    row_gemv(E0, w, lane, a0, a1);
    g_E1[(size_t)w * DIM + lane]      = a0;
    g_E1[(size_t)w * DIM + lane + 32] = a1;
}

__global__ void __launch_bounds__(256) k_spmm2() {
    int w    = (blockIdx.x * blockDim.x + threadIdx.x) >> 5;
    int lane = threadIdx.x & 31;
    if (w >= N_TOTAL) return;
    float a0, a1;
    row_gemv(g_E1, w, lane, a0, a1);
    g_E2[(size_t)w * DIM + lane]      = a0;
    g_E2[(size_t)w * DIM + lane + 32] = a1;
}

// ---------------- fused layer-3 + average + gather ----------------
// out slots: 0 u_emb, 1 pos_emb, 2 neg_emb, 3 u_emb0, 4 pos_emb0, 5 neg_emb0
__global__ void __launch_bounds__(256) k_gather(const int* __restrict__ users,
                                                const int* __restrict__ pos,
                                                const int* __restrict__ neg,
                                                const float* __restrict__ E0,
                                                float* __restrict__ out) {
    int w    = (blockIdx.x * blockDim.x + threadIdx.x) >> 5;
    int lane = threadIdx.x & 31;
    if (w >= 3 * BATCH) return;
    int slot = w / BATCH;
    int b    = w - slot * BATCH;
    int r;
    if (slot == 0)      r = users[b];
    else if (slot == 1) r = N_USERS + pos[b];
    else                r = N_USERS + neg[b];

    // E3 row = (A @ E2)[r] — only needed at gathered rows
    float a0, a1;
    row_gemv(g_E2, r, lane, a0, a1);

    size_t ro = (size_t)r * DIM;
    float e0a = E0[ro + lane],        e0b = E0[ro + lane + 32];
    float f0  = (e0a + g_E1[ro + lane]      + g_E2[ro + lane]      + a0) * 0.25f;
    float f1  = (e0b + g_E1[ro + lane + 32] + g_E2[ro + lane + 32] + a1) * 0.25f;

    size_t base  = (size_t)slot * BATCH * DIM + (size_t)b * DIM;
    size_t base0 = (size_t)(slot + 3) * BATCH * DIM + (size_t)b * DIM;
    out[base  + lane]      = f0;
    out[base  + lane + 32] = f1;
    out[base0 + lane]      = e0a;
    out[base0 + lane + 32] = e0b;
}

// ---------------- launch ----------------

extern "C" void kernel_launch(void* const* d_in, const int* in_sizes, int n_in,
                              void* d_out, int out_size) {
    const int*   users = (const int*)  d_in[0];
    const int*   pos   = (const int*)  d_in[1];
    const int*   neg   = (const int*)  d_in[2];
    const float* E0    = (const float*)d_in[3];
    const int*   arow  = (const int*)  d_in[4];
    const int*   acol  = (const int*)  d_in[5];
    const float* avals = (const float*)d_in[6];
    float* out = (float*)d_out;

    const int e4_blocks = (NNZ / 4 + 255) / 256;   // 1172

    k_zero<<<(N_TOTAL + 255) / 256, 256>>>();
    k_hist<<<e4_blocks, 256>>>((const int4*)arow);
    k_scan1<<<NBLK_SCAN, SCAN_B>>>();              // includes fused block-sum scan
    k_scan3<<<(N_TOTAL + 255) / 256, 256>>>();
    k_scatter<<<e4_blocks, 256>>>((const int4*)arow, (const int4*)acol, (const float4*)avals);

    const int spmm_blocks = (N_TOTAL * 32 + 255) / 256;   // 1 warp per row
    k_spmm1<<<spmm_blocks, 256>>>(E0);
    k_spmm2<<<spmm_blocks, 256>>>();

    const int gat_blocks = (3 * BATCH * 32 + 255) / 256;
    k_gather<<<gat_blocks, 256>>>(users, pos, neg, E0, out);
}

// round 9
// speedup vs baseline: 1.6511x; 1.0495x over previous
#include <cuda_runtime.h>
#include <cuda_fp16.h>

#define N_USERS  100000
#define N_ITEMS  50000
#define N_TOTAL  150000
#define DIM      64
#define NNZ      1200000
#define BATCH    4096
#define SCAN_B   1024
#define NBLK_SCAN ((N_TOTAL + SCAN_B - 1) / SCAN_B)   // 147

// ---- scratch (device globals; no allocation allowed) ----
__device__ int      g_count[N_TOTAL];
__device__ int      g_rowptr[N_TOTAL];       // excl prefix; scatter turns it into end(r)
__device__ int      g_bsum[NBLK_SCAN];
__device__ unsigned g_scan_done;             // zero-init; reset by last block
__device__ int2     g_csr[NNZ];              // {col, val bits} interleaved
__device__ __half2  g_E1h[N_TOTAL * 32];     // half2 = (dim lane, dim lane+32)
__device__ __half2  g_E2h[N_TOTAL * 32];

// ---------------- CSR build ----------------

__global__ void k_zero() {
    int i = blockIdx.x * blockDim.x + threadIdx.x;
    if (i < N_TOTAL) g_count[i] = 0;
}

// 4 edges per thread — 4 independent atomics in flight
__global__ void k_hist(const int4* __restrict__ row4) {
    int t = blockIdx.x * blockDim.x + threadIdx.x;
    if (t < NNZ / 4) {
        int4 r = row4[t];
        atomicAdd(&g_count[r.x], 1);
        atomicAdd(&g_count[r.y], 1);
        atomicAdd(&g_count[r.z], 1);
        atomicAdd(&g_count[r.w], 1);
    }
}

// per-block exclusive scan (shfl-based, 2 barriers); last block scans the block sums
__global__ void __launch_bounds__(SCAN_B) k_scan1() {
    __shared__ int  wsum[32];
    __shared__ bool is_last;
    int tid  = threadIdx.x;
    int lane = tid & 31, wid = tid >> 5;
    int i = blockIdx.x * SCAN_B + tid;
    int v = (i < N_TOTAL) ? g_count[i] : 0;

    int x = v;
    #pragma unroll
    for (int off = 1; off < 32; off <<= 1) {
        int t = __shfl_up_sync(0xffffffffu, x, off);
        if (lane >= off) x += t;
    }
    if (lane == 31) wsum[wid] = x;
    __syncthreads();
    if (wid == 0) {
        int s = wsum[lane];
        #pragma unroll
        for (int off = 1; off < 32; off <<= 1) {
            int t = __shfl_up_sync(0xffffffffu, s, off);
            if (lane >= off) s += t;
        }
        wsum[lane] = s;
    }
    __syncthreads();
    int incl = x + (wid ? wsum[wid - 1] : 0);
    if (i < N_TOTAL) g_rowptr[i] = incl - v;          // exclusive within block
    if (tid == SCAN_B - 1) g_bsum[blockIdx.x] = incl;

    // fold the block-sum scan into the last block to finish
    __threadfence();
    if (tid == 0)
        is_last = (atomicAdd(&g_scan_done, 1u) == (unsigned)(gridDim.x - 1));
    __syncthreads();
    if (is_last && tid < 32) {
        int carry = 0;
        for (int base = 0; base < NBLK_SCAN; base += 32) {
            int bi = base + lane;
            int bv = (bi < NBLK_SCAN) ? g_bsum[bi] : 0;
            int y = bv;
            #pragma unroll
            for (int off = 1; off < 32; off <<= 1) {
                int t = __shfl_up_sync(0xffffffffu, y, off);
                if (lane >= off) y += t;
            }
            if (bi < NBLK_SCAN) g_bsum[bi] = y - bv + carry;   // exclusive + carry
            carry += __shfl_sync(0xffffffffu, y, 31);
        }
        if (lane == 0) g_scan_done = 0u;                       // reset for next replay
    }
}

__global__ void k_scan3() {
    int i = blockIdx.x * blockDim.x + threadIdx.x;
    if (i < N_TOTAL) g_rowptr[i] += g_bsum[i / SCAN_B];
}

// 4 edges per thread; bumps rowptr in place (rowptr[r] becomes end(r))
__global__ void k_scatter(const int4* __restrict__ row4,
                          const int4* __restrict__ col4,
                          const float4* __restrict__ val4) {
    int t = blockIdx.x * blockDim.x + threadIdx.x;
    if (t < NNZ / 4) {
        int4   r = row4[t];
        int4   c = col4[t];
        float4 v = val4[t];
        int p0 = atomicAdd(&g_rowptr[r.x], 1);
        int p1 = atomicAdd(&g_rowptr[r.y], 1);
        int p2 = atomicAdd(&g_rowptr[r.z], 1);
        int p3 = atomicAdd(&g_rowptr[r.w], 1);
        g_csr[p0] = make_int2(c.x, __float_as_int(v.x));
        g_csr[p1] = make_int2(c.y, __float_as_int(v.y));
        g_csr[p2] = make_int2(c.z, __float_as_int(v.z));
        g_csr[p3] = make_int2(c.w, __float_as_int(v.w));
    }
}

// ---------------- SpMM helpers ----------------
// post-scatter: start(r) = (r==0) ? 0 : rowptr[r-1], end(r) = rowptr[r]

__device__ __forceinline__ void row_range(int r, int& s, int& e) {
    s = (r == 0) ? 0 : g_rowptr[r - 1];
    e = g_rowptr[r];
}

// gather from fp32 table: scalar LDG.32 pairs (128B footprints — no replay penalty)
__device__ __forceinline__ void row_gemv_f(const float* __restrict__ E, int r, int lane,
                                           float& a0, float& a1) {
    int s, e; row_range(r, s, e);
    a0 = 0.f; a1 = 0.f;
    int j = s;
    for (; j + 2 <= e; j += 2) {
        int2 cv0 = g_csr[j];
        int2 cv1 = g_csr[j + 1];
        const float* __restrict__ e0 = E + (size_t)cv0.x * DIM;
        const float* __restrict__ e1 = E + (size_t)cv1.x * DIM;
        float x00 = e0[lane], x01 = e0[lane + 32];
        float x10 = e1[lane], x11 = e1[lane + 32];
        float v0 = __int_as_float(cv0.y), v1 = __int_as_float(cv1.y);
        a0 = fmaf(v0, x00, a0); a1 = fmaf(v0, x01, a1);
        a0 = fmaf(v1, x10, a0); a1 = fmaf(v1, x11, a1);
    }
    if (j < e) {
        int2 cv = g_csr[j];
        const float* __restrict__ e0 = E + (size_t)cv.x * DIM;
        float v0 = __int_as_float(cv.y);
        a0 = fmaf(v0, e0[lane],      a0);
        a1 = fmaf(v0, e0[lane + 32], a1);
    }
}

// gather from fp16 table: one LDG.32 per neighbor (128B/warp), fp32 accumulate
__device__ __forceinline__ void row_gemv_h(const __half2* __restrict__ Eh, int r, int lane,
                                           float& a0, float& a1) {
    int s, e; row_range(r, s, e);
    a0 = 0.f; a1 = 0.f;
    int j = s;
    for (; j + 2 <= e; j += 2) {
        int2 cv0 = g_csr[j];
        int2 cv1 = g_csr[j + 1];
        float2 x0 = __half22float2(Eh[(size_t)cv0.x * 32 + lane]);
        float2 x1 = __half22float2(Eh[(size_t)cv1.x * 32 + lane]);
        float v0 = __int_as_float(cv0.y), v1 = __int_as_float(cv1.y);
        a0 = fmaf(v0, x0.x, a0); a1 = fmaf(v0, x0.y, a1);
        a0 = fmaf(v1, x1.x, a0); a1 = fmaf(v1, x1.y, a1);
    }
    if (j < e) {
        int2 cv = g_csr[j];
        float2 x0 = __half22float2(Eh[(size_t)cv.x * 32 + lane]);
        float v0 = __int_as_float(cv.y);
        a0 = fmaf(v0, x0.x, a0);
        a1 = fmaf(v0, x0.y, a1);
    }
}

__global__ void __launch_bounds__(256) k_spmm1(const float* __restrict__ E0) {
    int w    = (blockIdx.x * blockDim.x + threadIdx.x) >> 5;
    int lane = threadIdx.x & 31;
    if (w >= N_TOTAL) return;
    float a0, a1;
    row_gemv_f(E0, w, lane, a0, a1);
    g_E1h[(size_t)w * 32 + lane] = __float22half2_rn(make_float2(a0, a1));
}

__global__ void __launch_bounds__(256) k_spmm2() {
    int w    = (blockIdx.x * blockDim.x + threadIdx.x) >> 5;
    int lane = threadIdx.x & 31;
    if (w >= N_TOTAL) return;
    float a0, a1;
    row_gemv_h(g_E1h, w, lane, a0, a1);
    g_E2h[(size_t)w * 32 + lane] = __float22half2_rn(make_float2(a0, a1));
}

// ---------------- fused layer-3 + average + gather ----------------
// out slots: 0 u_emb, 1 pos_emb, 2 neg_emb, 3 u_emb0, 4 pos_emb0, 5 neg_emb0
__global__ void __launch_bounds__(256) k_gather(const int* __restrict__ users,
                                                const int* __restrict__ pos,
                                                const int* __restrict__ neg,
                                                const float* __restrict__ E0,
                                                float* __restrict__ out) {
    int w    = (blockIdx.x * blockDim.x + threadIdx.x) >> 5;
    int lane = threadIdx.x & 31;
    if (w >= 3 * BATCH) return;
    int slot = w / BATCH;
    int b    = w - slot * BATCH;
    int r;
    if (slot == 0)      r = users[b];
    else if (slot == 1) r = N_USERS + pos[b];
    else                r = N_USERS + neg[b];

    // E3 row = (A @ E2)[r] — only needed at gathered rows
    float a0, a1;
    row_gemv_h(g_E2h, r, lane, a0, a1);

    size_t ro = (size_t)r * DIM;
    float  e0a = E0[ro + lane], e0b = E0[ro + lane + 32];
    float2 e1  = __half22float2(g_E1h[(size_t)r * 32 + lane]);
    float2 e2  = __half22float2(g_E2h[(size_t)r * 32 + lane]);
    float f0 = (e0a + e1.x + e2.x + a0) * 0.25f;
    float f1 = (e0b + e1.y + e2.y + a1) * 0.25f;

    size_t base  = (size_t)slot * BATCH * DIM + (size_t)b * DIM;
    size_t base0 = (size_t)(slot + 3) * BATCH * DIM + (size_t)b * DIM;
    out[base  + lane]      = f0;
    out[base  + lane + 32] = f1;
    out[base0 + lane]      = e0a;
    out[base0 + lane + 32] = e0b;
}

// ---------------- launch ----------------

extern "C" void kernel_launch(void* const* d_in, const int* in_sizes, int n_in,
                              void* d_out, int out_size) {
    const int*   users = (const int*)  d_in[0];
    const int*   pos   = (const int*)  d_in[1];
    const int*   neg   = (const int*)  d_in[2];
    const float* E0    = (const float*)d_in[3];
    const int*   arow  = (const int*)  d_in[4];
    const int*   acol  = (const int*)  d_in[5];
    const float* avals = (const float*)d_in[6];
    float* out = (float*)d_out;

    const int e4_blocks = (NNZ / 4 + 255) / 256;   // 1172

    k_zero<<<(N_TOTAL + 255) / 256, 256>>>();
    k_hist<<<e4_blocks, 256>>>((const int4*)arow);
    k_scan1<<<NBLK_SCAN, SCAN_B>>>();              // includes fused block-sum scan
    k_scan3<<<(N_TOTAL + 255) / 256, 256>>>();
    k_scatter<<<e4_blocks, 256>>>((const int4*)arow, (const int4*)acol, (const float4*)avals);

    const int spmm_blocks = (N_TOTAL * 32 + 255) / 256;   // 1 warp per row
    k_spmm1<<<spmm_blocks, 256>>>(E0);
    k_spmm2<<<spmm_blocks, 256>>>();

    const int gat_blocks = (3 * BATCH * 32 + 255) / 256;
    k_gather<<<gat_blocks, 256>>>(users, pos, neg, E0, out);
}